// round 5
// baseline (speedup 1.0000x reference)
#include <cuda_runtime.h>
#include <stdint.h>
#include <cub/cub.cuh>

// ---------------------------------------------------------------------------
// Sparse average pooling, sort-based.
//
// The reference runs under JAX default x64-disabled: its int64 key
//   ((b*2048 + q0)*2048 + q1)*2048 + q2
// is computed in int32, where b*2^33 wraps to 0 (mod 2^32). The effective key
// is q0*2^22 + q1*2^11 + q2 (< 2^31, positive): BATCH IS DROPPED, voxels merge
// across batches, sort order is lex (q0, q1, q2).
//
// key = (q0<<18)|(q1<<9)|q2, 27 bits, order-isomorphic to the effective key.
// rank(point) = position of its key in the ascending sorted unique key set.
// Built by: radix-sort (key, point) pairs -> head flags -> inclusive scan.
// ---------------------------------------------------------------------------

#define MAXN (1 << 21)

__device__ uint32_t g_keys[MAXN];     // unsorted keys; reused as head flags after sort
__device__ uint32_t g_vals[MAXN];     // point indices
__device__ uint32_t g_keys_s[MAXN];   // sorted keys
__device__ uint32_t g_vals_s[MAXN];   // point indices in sorted-key order
__device__ uint32_t g_rank1[MAXN];    // inclusive scan of flags = rank + 1
__device__ uint32_t g_counts[MAXN];   // points per unique voxel
__device__ unsigned char g_temp[64u * 1024u * 1024u];  // CUB temp storage

__device__ __forceinline__ uint32_t make_key(int4 c) {
    uint32_t q0 = ((uint32_t)c.x) >> 1;   // floor(x/2), x in [0,1000)
    uint32_t q1 = ((uint32_t)c.y) >> 1;
    uint32_t q2 = ((uint32_t)c.z) >> 1;
    return (q0 << 18) | (q1 << 9) | q2;   // batch intentionally excluded
}

// K1: build (key, index) pairs; zero counts.
__global__ void k_makekeys(const int4* __restrict__ coords, int n) {
    int i = blockIdx.x * blockDim.x + threadIdx.x;
    if (i >= n) return;
    g_keys[i]   = make_key(coords[i]);
    g_vals[i]   = (uint32_t)i;
    g_counts[i] = 0u;
}

// K2: head flags over sorted keys (1 where a new unique key starts).
__global__ void k_flags(int n) {
    int i = blockIdx.x * blockDim.x + threadIdx.x;
    if (i >= n) return;
    uint32_t f = (i == 0) ? 1u : (g_keys_s[i] != g_keys_s[i - 1] ? 1u : 0u);
    g_keys[i] = f;   // reuse g_keys as flag storage
}

// K3: per-voxel counts from ranks.
__global__ void k_count(int n) {
    int i = blockIdx.x * blockDim.x + threadIdx.x;
    if (i >= n) return;
    atomicAdd(&g_counts[g_rank1[i] - 1u], 1u);
}

// K4: zero empty (count==0) and multi (count>1) output slots.
//     count==1 slots are fully overwritten by K5, no init needed.
__global__ void k_prep(float* __restrict__ outc, float* __restrict__ outf, int n) {
    int s = blockIdx.x * blockDim.x + threadIdx.x;
    if (s >= n) return;
    if (g_counts[s] != 1u) {
        float4 z = make_float4(0.f, 0.f, 0.f, 0.f);
        reinterpret_cast<float4*>(outc + 4ull * s)[0] = z;
        float4* f = reinterpret_cast<float4*>(outf + 64ull * s);
#pragma unroll
        for (int j = 0; j < 16; j++) f[j] = z;
    }
}

// K5: scatter. One warp per sorted position: count==1 -> direct store
//     (no atomics); else atomic accumulate into zeroed slot.
__global__ void k_scatter(const int* __restrict__ coords, const float* __restrict__ feats,
                          float* __restrict__ outc, float* __restrict__ outf, int n) {
    uint32_t gw   = (blockIdx.x * blockDim.x + threadIdx.x) >> 5;
    uint32_t lane = threadIdx.x & 31u;
    if (gw >= (uint32_t)n) return;
    uint32_t r = g_rank1[gw] - 1u;       // voxel slot
    uint32_t p = g_vals_s[gw];           // source point
    uint32_t c = g_counts[r];

    const float2* fin = reinterpret_cast<const float2*>(feats + 64ull * p);
    float2 v = fin[lane];
    float2* fo = reinterpret_cast<float2*>(outf + 64ull * r);

    if (c == 1u) {
        fo[lane] = v;
        if (lane < 4u) outc[4ull * r + lane] = (float)coords[4ull * p + lane];
    } else {
        float* fs = outf + 64ull * r + 2ull * lane;
        atomicAdd(fs, v.x);
        atomicAdd(fs + 1, v.y);
        if (lane < 4u) atomicAdd(&outc[4ull * r + lane], (float)coords[4ull * p + lane]);
    }
}

// K6: finalize multi-point voxels: divide by count; coords rounded half-to-even
//     (rintf == jnp.round; integer sums are exact in f32, so rounding matches
//     the reference bit-for-bit).
__global__ void k_final(float* __restrict__ outc, float* __restrict__ outf, int n) {
    int s = blockIdx.x * blockDim.x + threadIdx.x;
    if (s >= n) return;
    uint32_t c = g_counts[s];
    if (c > 1u) {
        float fc = (float)c;
#pragma unroll
        for (int j = 0; j < 4; j++)
            outc[4ull * s + j] = rintf(outc[4ull * s + j] / fc);
#pragma unroll
        for (int j = 0; j < 64; j++)
            outf[64ull * s + j] = outf[64ull * s + j] / fc;
    }
}

extern "C" void kernel_launch(void* const* d_in, const int* in_sizes, int n_in,
                              void* d_out, int out_size) {
    // coords is the smaller input (4 ints/point) vs feats (64 floats/point)
    const int*   coords;
    const float* feats;
    int n;
    if (in_sizes[0] <= in_sizes[1]) {
        coords = (const int*)d_in[0];
        feats  = (const float*)d_in[1];
        n = in_sizes[0] / 4;
    } else {
        coords = (const int*)d_in[1];
        feats  = (const float*)d_in[0];
        n = in_sizes[1] / 4;
    }
    if (n <= 0 || n > MAXN) return;

    float* outc = (float*)d_out;             // [n,4]  pooled coords (as f32)
    float* outf = outc + 4ull * (size_t)n;   // [n,64] pooled feats

    const int4* c4 = reinterpret_cast<const int4*>(coords);
    int nb = (n + 255) / 256;

    void *keys, *vals, *keys_s, *vals_s, *rank1, *temp;
    cudaGetSymbolAddress(&keys,   g_keys);
    cudaGetSymbolAddress(&vals,   g_vals);
    cudaGetSymbolAddress(&keys_s, g_keys_s);
    cudaGetSymbolAddress(&vals_s, g_vals_s);
    cudaGetSymbolAddress(&rank1,  g_rank1);
    cudaGetSymbolAddress(&temp,   g_temp);

    k_makekeys<<<nb, 256>>>(c4, n);

    // Radix sort (key, point-index) pairs on 27 key bits.
    size_t tb = 0;
    cub::DeviceRadixSort::SortPairs(nullptr, tb,
        (const uint32_t*)keys, (uint32_t*)keys_s,
        (const uint32_t*)vals, (uint32_t*)vals_s, n, 0, 27);
    if (tb > sizeof(g_temp)) return;
    cub::DeviceRadixSort::SortPairs(temp, tb,
        (const uint32_t*)keys, (uint32_t*)keys_s,
        (const uint32_t*)vals, (uint32_t*)vals_s, n, 0, 27);

    k_flags<<<nb, 256>>>(n);

    // rank+1 = inclusive scan of head flags.
    size_t tb2 = 0;
    cub::DeviceScan::InclusiveSum(nullptr, tb2,
        (const uint32_t*)keys, (uint32_t*)rank1, n);
    if (tb2 > sizeof(g_temp)) return;
    cub::DeviceScan::InclusiveSum(temp, tb2,
        (const uint32_t*)keys, (uint32_t*)rank1, n);

    k_count<<<nb, 256>>>(n);
    k_prep<<<nb, 256>>>(outc, outf, n);
    {
        long long threads = 32ll * n;
        int blocks = (int)((threads + 255) / 256);
        k_scatter<<<blocks, 256>>>(coords, feats, outc, outf, n);
    }
    k_final<<<nb, 256>>>(outc, outf, n);
}

// round 6
// speedup vs baseline: 1.1316x; 1.1316x over previous
#include <cuda_runtime.h>
#include <stdint.h>

// ---------------------------------------------------------------------------
// Sparse average pooling via L2-resident presence-bitmap ranks.
//
// Effective reference key (JAX x64 disabled, int32 wrap kills the batch term):
//   q0*2^22 + q1*2^11 + q2   with  q_i = coord_i >> 1 < 512.
// Order-isomorphic 27-bit key: (q0<<18)|(q1<<9)|q2. Bitmap = 2^27 bits = 16MB
// (fits L2). rank = # distinct smaller keys present = jnp.unique inverse.
// Rank machinery identical to the proven sort-equivalent pipeline.
// ---------------------------------------------------------------------------

#define NBM_WORDS (1u << 22)   // 2^27 bits / 32 = 4,194,304 words (16 MB)
#define NSEG      (1u << 17)   // 32 words (1024 bits) per segment
#define NCHUNK    128          // NSEG / 1024
#define MAXN      (1  << 21)

__device__ uint32_t g_bitmap[NBM_WORDS];
__device__ uint32_t g_segpref[NSEG];   // per-segment popcount -> chunk-local exclusive prefix
__device__ uint32_t g_part[NCHUNK];    // chunk sums -> exclusive prefix of chunks
__device__ uint32_t g_counts[MAXN];
__device__ uint32_t g_ranks[MAXN];

__device__ __forceinline__ uint32_t make_key(int4 c) {
    uint32_t q0 = ((uint32_t)c.x) >> 1;
    uint32_t q1 = ((uint32_t)c.y) >> 1;
    uint32_t q2 = ((uint32_t)c.z) >> 1;
    return (q0 << 18) | (q1 << 9) | q2;   // batch excluded (int32 wrap in reference)
}

// K1: zero bitmap + counts
__global__ void k_zero(int n) {
    int tid = blockIdx.x * blockDim.x + threadIdx.x;
    int stride = gridDim.x * blockDim.x;
    uint4 z = make_uint4(0u, 0u, 0u, 0u);
    uint4* bm = reinterpret_cast<uint4*>(g_bitmap);
    for (uint32_t i = tid; i < NBM_WORDS / 4; i += stride) bm[i] = z;
    for (uint32_t i = tid; i < (uint32_t)n; i += stride) g_counts[i] = 0u;
}

// K2: set presence bits
__global__ void k_setbits(const int4* __restrict__ coords, int n) {
    int i = blockIdx.x * blockDim.x + threadIdx.x;
    if (i >= n) return;
    uint32_t key = make_key(coords[i]);
    atomicOr(&g_bitmap[key >> 5], 1u << (key & 31u));
}

// K3: per-segment popcount (warp per 1024-bit segment, fully coalesced)
__global__ void k_segcnt() {
    uint32_t gw   = (blockIdx.x * blockDim.x + threadIdx.x) >> 5;
    uint32_t lane = threadIdx.x & 31u;
    if (gw >= NSEG) return;
    uint32_t v = g_bitmap[(gw << 5) + lane];
    uint32_t s = __reduce_add_sync(0xffffffffu, __popc(v));
    if (lane == 0) g_segpref[gw] = s;
}

// K4a: exclusive scan of g_segpref within 1024-element chunks; chunk sums -> g_part
__global__ void k_scan1() {
    __shared__ uint32_t sh[1024];
    uint32_t idx = blockIdx.x * 1024u + threadIdx.x;
    uint32_t v = g_segpref[idx];
    sh[threadIdx.x] = v;
    __syncthreads();
    for (int off = 1; off < 1024; off <<= 1) {
        uint32_t t = 0;
        if ((int)threadIdx.x >= off) t = sh[threadIdx.x - off];
        __syncthreads();
        if ((int)threadIdx.x >= off) sh[threadIdx.x] += t;
        __syncthreads();
    }
    uint32_t incl = sh[threadIdx.x];
    g_segpref[idx] = incl - v;             // exclusive within chunk
    if (threadIdx.x == 1023) g_part[blockIdx.x] = incl;
}

// K4b: exclusive scan of the NCHUNK chunk sums (single block)
__global__ void k_scan2() {
    __shared__ uint32_t sh[NCHUNK];
    uint32_t v = g_part[threadIdx.x];
    sh[threadIdx.x] = v;
    __syncthreads();
    for (int off = 1; off < NCHUNK; off <<= 1) {
        uint32_t t = 0;
        if ((int)threadIdx.x >= off) t = sh[threadIdx.x - off];
        __syncthreads();
        if ((int)threadIdx.x >= off) sh[threadIdx.x] += t;
        __syncthreads();
    }
    g_part[threadIdx.x] = sh[threadIdx.x] - v;  // exclusive
}

// K5: per-point rank (= unique inverse index) + voxel counts. All L2-hot.
__global__ void k_rank(const int4* __restrict__ coords, int n) {
    int i = blockIdx.x * blockDim.x + threadIdx.x;
    if (i >= n) return;
    uint32_t key  = make_key(coords[i]);
    uint32_t bit  = key & 31u;
    uint32_t w    = key >> 5;
    uint32_t seg  = w >> 5;
    uint32_t widx = w & 31u;

    uint32_t r = g_part[seg >> 10] + g_segpref[seg];
    uint32_t mask = (1u << bit) - 1u;   // bits strictly below 'bit'

    const uint4* p = reinterpret_cast<const uint4*>(&g_bitmap[seg << 5]);
#pragma unroll
    for (int j = 0; j < 8; j++) {
        uint4 v = p[j];
        uint32_t base = (uint32_t)(j * 4);
#pragma unroll
        for (int k = 0; k < 4; k++) {
            uint32_t word = (k == 0) ? v.x : (k == 1) ? v.y : (k == 2) ? v.z : v.w;
            uint32_t idx = base + (uint32_t)k;
            if (idx < widx)       r += __popc(word);
            else if (idx == widx) r += __popc(word & mask);
        }
    }
    g_ranks[i] = r;
    atomicAdd(&g_counts[r], 1u);
}

// K6: zero empty (count==0) and multi (count>1) output slots.
//     count==1 slots (~99%+) are fully overwritten by K7, no init needed.
__global__ void k_prep(float* __restrict__ outc, float* __restrict__ outf, int n) {
    int s = blockIdx.x * blockDim.x + threadIdx.x;
    if (s >= n) return;
    if (g_counts[s] != 1u) {
        float4 z = make_float4(0.f, 0.f, 0.f, 0.f);
        reinterpret_cast<float4*>(outc + 4ull * s)[0] = z;
        float4* f = reinterpret_cast<float4*>(outf + 64ull * s);
#pragma unroll
        for (int j = 0; j < 16; j++) f[j] = z;
    }
}

// K7: scatter. Warp per point (sequential feat reads): count==1 -> direct
//     store (no atomics); else atomic accumulate into zeroed slot.
__global__ void k_scatter(const int* __restrict__ coords, const float* __restrict__ feats,
                          float* __restrict__ outc, float* __restrict__ outf, int n) {
    uint32_t gw   = (blockIdx.x * blockDim.x + threadIdx.x) >> 5;
    uint32_t lane = threadIdx.x & 31u;
    if (gw >= (uint32_t)n) return;
    uint32_t r = g_ranks[gw];
    uint32_t c = g_counts[r];

    const float2* fin = reinterpret_cast<const float2*>(feats + 64ull * gw);
    float2 v = fin[lane];
    float2* fo = reinterpret_cast<float2*>(outf + 64ull * r);

    if (c == 1u) {
        fo[lane] = v;
        if (lane < 4u) outc[4ull * r + lane] = (float)coords[4ull * gw + lane];
    } else {
        float* fs = outf + 64ull * r + 2ull * lane;
        atomicAdd(fs, v.x);
        atomicAdd(fs + 1, v.y);
        if (lane < 4u) atomicAdd(&outc[4ull * r + lane], (float)coords[4ull * gw + lane]);
    }
}

// K8: finalize multi-point voxels: divide by count; coords rounded half-to-even
//     (rintf == jnp.round; integer sums are exact in f32 -> bit-exact rounding).
__global__ void k_final(float* __restrict__ outc, float* __restrict__ outf, int n) {
    int s = blockIdx.x * blockDim.x + threadIdx.x;
    if (s >= n) return;
    uint32_t c = g_counts[s];
    if (c > 1u) {
        float fc = (float)c;
#pragma unroll
        for (int j = 0; j < 4; j++)
            outc[4ull * s + j] = rintf(outc[4ull * s + j] / fc);
#pragma unroll
        for (int j = 0; j < 64; j++)
            outf[64ull * s + j] = outf[64ull * s + j] / fc;
    }
}

extern "C" void kernel_launch(void* const* d_in, const int* in_sizes, int n_in,
                              void* d_out, int out_size) {
    // coords is the smaller input (4 ints/point) vs feats (64 floats/point)
    const int*   coords;
    const float* feats;
    int n;
    if (in_sizes[0] <= in_sizes[1]) {
        coords = (const int*)d_in[0];
        feats  = (const float*)d_in[1];
        n = in_sizes[0] / 4;
    } else {
        coords = (const int*)d_in[1];
        feats  = (const float*)d_in[0];
        n = in_sizes[1] / 4;
    }
    if (n <= 0 || n > MAXN) return;

    float* outc = (float*)d_out;             // [n,4]  pooled coords (as f32)
    float* outf = outc + 4ull * (size_t)n;   // [n,64] pooled feats

    const int4* c4 = reinterpret_cast<const int4*>(coords);
    int nb = (n + 255) / 256;

    k_zero<<<2048, 256>>>(n);
    k_setbits<<<nb, 256>>>(c4, n);
    k_segcnt<<<NSEG * 32 / 256, 256>>>();
    k_scan1<<<NCHUNK, 1024>>>();
    k_scan2<<<1, NCHUNK>>>();
    k_rank<<<nb, 256>>>(c4, n);
    k_prep<<<nb, 256>>>(outc, outf, n);
    {
        long long threads = 32ll * n;
        int blocks = (int)((threads + 255) / 256);
        k_scatter<<<blocks, 256>>>(coords, feats, outc, outf, n);
    }
    k_final<<<nb, 256>>>(outc, outf, n);
}